// round 14
// baseline (speedup 1.0000x reference)
#include <cuda_runtime.h>
#include <cuda_fp16.h>
#include <cstdint>

#define NN   50000
#define EE   800000
#define IN_F 256
#define HID_F 256
#define OUT_F 128

// ---------------- static device scratch (no allocation allowed) ----------------
__device__ int   g_cnt[NN];
__device__ int   g_rowptr[NN + 1];
__device__ int   g_cursor[NN];
__device__ int2  g_srt[EE];           // (src, weight-bits) interleaved

// fp16 activation buffers (hi-only representation)
__device__ __half g_F16[NN * 256];    // features, fp16
__device__ __half g_T1[NN * 256];     // A @ X, fp16
__device__ __half g_H1[NN * 256];     // h1, fp16
__device__ __half g_HID[NN * 256];    // MLP hidden, fp16
__device__ __half g_B3h[NN * 128];    // h1 @ W2 (pre-spmm2), fp16

// fp16 transposed weights  B[n][k] = W[k][n]  (hi only)
__device__ __half g_W1h[256 * 256];
__device__ __half g_W2h[128 * 256];
__device__ __half g_M1h[256 * 256];
__device__ __half g_M2h[128 * 256];

// ---------------- PTX helpers (sm_80-era only: cp.async, ldmatrix, mma.sync) ----
__device__ __forceinline__ uint32_t smem_u32(const void* p) {
    uint32_t a;
    asm("{ .reg .u64 t; cvta.to.shared.u64 t, %1; cvt.u32.u64 %0, t; }" : "=r"(a) : "l"(p));
    return a;
}
__device__ __forceinline__ void cp16(uint32_t d, const void* s) {
    asm volatile("cp.async.cg.shared.global [%0], [%1], 16;" :: "r"(d), "l"(s) : "memory");
}
#define CP_COMMIT() asm volatile("cp.async.commit_group;" ::: "memory")
#define CP_WAIT(n)  asm volatile("cp.async.wait_group %0;" :: "n"(n) : "memory")

#define LDSM4(r0, r1, r2, r3, a) \
    asm volatile("ldmatrix.sync.aligned.m8n8.x4.shared.b16 {%0,%1,%2,%3}, [%4];" \
                 : "=r"(r0), "=r"(r1), "=r"(r2), "=r"(r3) : "r"(a))

#define MMA16816(c, a, b) \
    asm volatile("mma.sync.aligned.m16n8k16.row.col.f32.f16.f16.f32 " \
                 "{%0,%1,%2,%3}, {%4,%5,%6,%7}, {%8,%9}, {%0,%1,%2,%3};" \
                 : "+f"((c)[0]), "+f"((c)[1]), "+f"((c)[2]), "+f"((c)[3]) \
                 : "r"((a)[0]), "r"((a)[1]), "r"((a)[2]), "r"((a)[3]), \
                   "r"((b)[0]), "r"((b)[1]))

__device__ __forceinline__ uint32_t swz(uint32_t o) { return o ^ ((o >> 3) & 0x70); }

// ---------------- CSR build ----------------
__global__ void k_clear_cnt() {
    int i = blockIdx.x * blockDim.x + threadIdx.x;
    if (i < NN) g_cnt[i] = 0;
}

__global__ void k_hist(const int* __restrict__ dst) {
    int e = blockIdx.x * blockDim.x + threadIdx.x;
    if (e < EE) atomicAdd(&g_cnt[dst[e]], 1);
}

__global__ void k_scan() {
    __shared__ int warp_sums[32];
    int t = threadIdx.x;
    int lane = t & 31, wid = t >> 5;
    int carry = 0;
    for (int base = 0; base < NN; base += 1024) {
        int i = base + t;
        int v = (i < NN) ? g_cnt[i] : 0;
        int x = v;
        #pragma unroll
        for (int o = 1; o < 32; o <<= 1) {
            int y = __shfl_up_sync(0xFFFFFFFFu, x, o);
            if (lane >= o) x += y;
        }
        if (lane == 31) warp_sums[wid] = x;
        __syncthreads();
        if (wid == 0) {
            int s = warp_sums[lane];
            #pragma unroll
            for (int o = 1; o < 32; o <<= 1) {
                int y = __shfl_up_sync(0xFFFFFFFFu, s, o);
                if (lane >= o) s += y;
            }
            warp_sums[lane] = s;
        }
        __syncthreads();
        int warp_off = (wid == 0) ? 0 : warp_sums[wid - 1];
        int excl = carry + warp_off + x - v;
        if (i < NN) { g_rowptr[i] = excl; g_cursor[i] = excl; }
        int tot = warp_sums[31];
        __syncthreads();
        carry += tot;
    }
    if (t == 0) g_rowptr[NN] = carry;
}

__global__ void k_scatter(const int* __restrict__ src, const int* __restrict__ dst,
                          const float* __restrict__ w) {
    int e = blockIdx.x * blockDim.x + threadIdx.x;
    if (e < EE) {
        int p = atomicAdd(&g_cursor[dst[e]], 1);
        g_srt[p] = make_int2(src[e], __float_as_int(w[e]));
    }
}

// ---------------- gather SpMM over fp16 source (warp per dst node) -------------
__global__ __launch_bounds__(256) void k_spmm256h(const __half* __restrict__ x16,
                                                  __half* __restrict__ y16) {
    int gw = (blockIdx.x * blockDim.x + threadIdx.x) >> 5;
    if (gw >= NN) return;
    int lane = threadIdx.x & 31;
    float a[8];
    #pragma unroll
    for (int i = 0; i < 8; i++) a[i] = 0.f;
    int s = g_rowptr[gw], e = g_rowptr[gw + 1];
    for (int i = s; i < e; i++) {
        int2  ew  = g_srt[i];
        float w   = __int_as_float(ew.y);
        uint4 v = *(const uint4*)(x16 + (size_t)ew.x * 256 + lane * 8);
        const __half2* h = (const __half2*)&v;
        #pragma unroll
        for (int j = 0; j < 4; j++) {
            float2 f = __half22float2(h[j]);
            a[2*j + 0] += w * f.x;
            a[2*j + 1] += w * f.y;
        }
    }
    uint4 o;
    __half2* oh = (__half2*)&o;
    #pragma unroll
    for (int j = 0; j < 4; j++)
        oh[j] = __floats2half2_rn(a[2*j], a[2*j + 1]);
    *(uint4*)(y16 + (size_t)gw * 256 + lane * 8) = o;
}

// fp16 gather SpMM for the final hop: fp32 accum, fp32 output (direct to out).
__global__ __launch_bounds__(256) void k_spmm128h(const __half* __restrict__ x16,
                                                  float* __restrict__ y, int ldy) {
    int gw = (blockIdx.x * blockDim.x + threadIdx.x) >> 5;
    if (gw >= NN) return;
    int lane = threadIdx.x & 31;
    float a[4];
    #pragma unroll
    for (int i = 0; i < 4; i++) a[i] = 0.f;
    int s = g_rowptr[gw], e = g_rowptr[gw + 1];
    for (int i = s; i < e; i++) {
        int2  ew  = g_srt[i];
        float w   = __int_as_float(ew.y);
        uint2 v = *(const uint2*)(x16 + (size_t)ew.x * 128 + lane * 4);
        const __half2* h = (const __half2*)&v;
        #pragma unroll
        for (int j = 0; j < 2; j++) {
            float2 f = __half22float2(h[j]);
            a[2*j + 0] += w * f.x;
            a[2*j + 1] += w * f.y;
        }
    }
    *(float4*)(y + (size_t)gw * ldy + lane * 4) = make_float4(a[0], a[1], a[2], a[3]);
}

// ---------------- conversion kernels ----------------
__global__ void k_cvt_w(const float* __restrict__ W, __half* __restrict__ bh, int Nn) {
    int i = blockIdx.x * blockDim.x + threadIdx.x;
    if (i >= Nn * 256) return;
    int n = i >> 8, k = i & 255;
    bh[i] = __float2half_rn(W[k * Nn + n]);
}

__global__ void k_cvt_feat(const float4* __restrict__ f, __half* __restrict__ y) {
    int i = blockIdx.x * blockDim.x + threadIdx.x;
    if (i >= NN * 64) return;
    float4 v = f[i];
    __half2* o = (__half2*)(y + (size_t)i * 4);
    o[0] = __floats2half2_rn(v.x, v.y);
    o[1] = __floats2half2_rn(v.z, v.w);
}

// ---------------- plain fp16 GEMM on mma.sync (fp32 accum) ----------------
// D[128,128-tile] = A[M,256] @ B[Ntile,256]^T. K in 4 chunks of 64 halves.
// 3-stage cp.async pipeline, ONE __syncthreads per chunk (loads issued before
// compute; buffer (c+2)%3 was last read by compute(c-1), fenced by this sync).
// Stage layout (SW128 swizzled, 128B rows): +0 A (16KB), +16384 B (16KB).
#define STG_SZ   32768
#define N_STAGES 3

__global__ __launch_bounds__(256, 2) void k_hgemm(
    const __half* __restrict__ A,
    const __half* __restrict__ B,
    const float* __restrict__ bias,
    float* __restrict__ C, int ldc,
    __half* __restrict__ Ch, int ldch,
    int M, int relu)
{
    extern __shared__ char smem[];
    uint32_t sb = smem_u32(smem);

    int t    = threadIdx.x;
    int lane = t & 31;
    int wid  = t >> 5;
    int wm   = wid & 3;          // 4 warps along M (32 rows each)
    int wn   = wid >> 2;         // 2 warps along N (64 cols each)
    int bm   = blockIdx.y * 128;
    int bn   = blockIdx.x * 128;

    float acc[2][8][4];
    #pragma unroll
    for (int i = 0; i < 2; i++)
        #pragma unroll
        for (int j = 0; j < 8; j++)
            #pragma unroll
            for (int q = 0; q < 4; q++) acc[i][j][q] = 0.f;

    auto LOADC = [&](int c) {
        uint32_t st = sb + (c % N_STAGES) * STG_SZ;
        #pragma unroll
        for (int i = 0; i < 4; i++) {
            int id  = t + 256 * i;
            int row = id >> 3;
            int c16 = id & 7;
            uint32_t s = swz((uint32_t)row * 128 + c16 * 16);
            int ar = bm + row; if (ar >= M) ar = M - 1;
            size_t ga = (size_t)ar * 256 + c * 64 + c16 * 8;
            size_t gb = (size_t)(bn + row) * 256 + c * 64 + c16 * 8;
            cp16(st +         s, A + ga);
            cp16(st + 16384 + s, B + gb);
        }
        CP_COMMIT();
    };

    auto COMPUTE = [&](int c) {
        uint32_t st = sb + (c % N_STAGES) * STG_SZ;
        uint32_t bA = st, bB = st + 16384;
        #pragma unroll
        for (int ks = 0; ks < 4; ks++) {
            uint32_t ah[2][4], bh[8][2];
            #pragma unroll
            for (int i = 0; i < 2; i++) {
                uint32_t o = swz(((uint32_t)(wm * 32 + i * 16 + (lane & 15)) << 7)
                                 + ks * 32 + ((lane >> 4) << 4));
                LDSM4(ah[i][0], ah[i][1], ah[i][2], ah[i][3], bA + o);
            }
            #pragma unroll
            for (int j = 0; j < 8; j += 2) {
                uint32_t o = swz(((uint32_t)(wn * 64 + (j + (lane >> 4)) * 8 + (lane & 7)) << 7)
                                 + ks * 32 + (((lane >> 3) & 1) << 4));
                LDSM4(bh[j][0], bh[j][1], bh[j+1][0], bh[j+1][1], bB + o);
            }
            #pragma unroll
            for (int i = 0; i < 2; i++)
                #pragma unroll
                for (int j = 0; j < 8; j++)
                    MMA16816(acc[i][j], ah[i], bh[j]);
        }
    };

    // prologue: stages 0, 1 in flight
    LOADC(0);
    LOADC(1);

    #pragma unroll
    for (int c = 0; c < 4; c++) {
        if (c < 3) { CP_WAIT(1); } else { CP_WAIT(0); }
        __syncthreads();
        if (c + 2 < 4) LOADC(c + 2);   // overlaps with compute below
        COMPUTE(c);
    }

    // -------- epilogue: c-frag layout m16n8 --------
    int gid = lane >> 2;
    int qid = lane & 3;
    #pragma unroll
    for (int i = 0; i < 2; i++) {
        #pragma unroll
        for (int j = 0; j < 8; j++) {
            int col = bn + wn * 64 + j * 8 + qid * 2;
            float b0 = 0.f, b1 = 0.f;
            if (bias) { b0 = bias[col]; b1 = bias[col + 1]; }
            #pragma unroll
            for (int h = 0; h < 2; h++) {
                int gm = bm + wm * 32 + i * 16 + gid + h * 8;
                if (gm >= M) continue;
                float v0 = acc[i][j][2*h + 0] + b0;
                float v1 = acc[i][j][2*h + 1] + b1;
                if (relu) { v0 = fmaxf(v0, 0.f); v1 = fmaxf(v1, 0.f); }
                if (C) *(float2*)(C + (size_t)gm * ldc + col) = make_float2(v0, v1);
                if (Ch) *(__half2*)(Ch + (size_t)gm * ldch + col) = __floats2half2_rn(v0, v1);
            }
        }
    }
}

// ---------------- launch ----------------
extern "C" void kernel_launch(void* const* d_in, const int* in_sizes, int n_in,
                              void* d_out, int out_size) {
    const float* features = (const float*)d_in[0];
    const int*   edge_src = (const int*)d_in[1];
    const int*   edge_dst = (const int*)d_in[2];
    const float* edge_w   = (const float*)d_in[3];
    const float* W1       = (const float*)d_in[4];
    const float* W2       = (const float*)d_in[5];
    const float* mlp_w1   = (const float*)d_in[6];
    const float* mlp_b1   = (const float*)d_in[7];
    const float* mlp_w2   = (const float*)d_in[8];
    const float* mlp_b2   = (const float*)d_in[9];
    float* out = (float*)d_out;

    void* pv;
    cudaGetSymbolAddress(&pv, g_F16); __half* F16 = (__half*)pv;
    cudaGetSymbolAddress(&pv, g_T1);  __half* T1  = (__half*)pv;
    cudaGetSymbolAddress(&pv, g_H1);  __half* H1  = (__half*)pv;
    cudaGetSymbolAddress(&pv, g_HID); __half* HID = (__half*)pv;
    cudaGetSymbolAddress(&pv, g_B3h); __half* B3h = (__half*)pv;
    cudaGetSymbolAddress(&pv, g_W1h); __half* W1h = (__half*)pv;
    cudaGetSymbolAddress(&pv, g_W2h); __half* W2h = (__half*)pv;
    cudaGetSymbolAddress(&pv, g_M1h); __half* M1h = (__half*)pv;
    cudaGetSymbolAddress(&pv, g_M2h); __half* M2h = (__half*)pv;

    const int SMEM_BYTES = N_STAGES * STG_SZ;   // 98304/CTA, 2 CTAs/SM = 192KB
    cudaFuncSetAttribute(k_hgemm, cudaFuncAttributeMaxDynamicSharedMemorySize, SMEM_BYTES);

    const int E_BLKS = (EE + 255) / 256;
    const int N_BLKS = (NN + 255) / 256;
    const int SPMM_BLKS = (NN * 32 + 255) / 256;
    const int MT = (NN + 127) / 128;   // 391

    // -------- fork a second stream for conversions + the MLP branch --------
    cudaStream_t sB;
    cudaStreamCreateWithFlags(&sB, cudaStreamNonBlocking);
    cudaEvent_t evFork, evFeat, evW, evB;
    cudaEventCreateWithFlags(&evFork, cudaEventDisableTiming);
    cudaEventCreateWithFlags(&evFeat, cudaEventDisableTiming);
    cudaEventCreateWithFlags(&evW,    cudaEventDisableTiming);
    cudaEventCreateWithFlags(&evB,    cudaEventDisableTiming);

    cudaEventRecord(evFork, 0);
    cudaStreamWaitEvent(sB, evFork, 0);

    // ---- branch B (stream sB): all conversions + full MLP chain ----
    k_cvt_feat<<<(NN*64 + 255)/256, 256, 0, sB>>>((const float4*)features, F16);
    cudaEventRecord(evFeat, sB);
    k_cvt_w<<<(256*256 + 255)/256, 256, 0, sB>>>(W1,     W1h, 256);
    k_cvt_w<<<(128*256 + 255)/256, 256, 0, sB>>>(W2,     W2h, 128);
    cudaEventRecord(evW, sB);
    k_cvt_w<<<(256*256 + 255)/256, 256, 0, sB>>>(mlp_w1, M1h, 256);
    k_cvt_w<<<(128*256 + 255)/256, 256, 0, sB>>>(mlp_w2, M2h, 128);
    {   // hidden = relu(X @ mlp_w1 + b1) -> HID fp16
        dim3 grid(2, MT);
        k_hgemm<<<grid, 256, SMEM_BYTES, sB>>>(F16, M1h, mlp_b1,
                                               nullptr, 0, HID, 256, NN, 1);
    }
    {   // self_out = hidden @ mlp_w2 + b2 -> out[:,0:128]
        dim3 grid(1, MT);
        k_hgemm<<<grid, 256, SMEM_BYTES, sB>>>(HID, M2h, mlp_b2,
                                               out, 512, nullptr, 0, NN, 0);
    }
    cudaEventRecord(evB, sB);

    // ---- branch A (legacy stream): CSR build + conv chain ----
    k_clear_cnt<<<N_BLKS, 256>>>();
    k_hist<<<E_BLKS, 256>>>(edge_dst);
    k_scan<<<1, 1024>>>();
    k_scatter<<<E_BLKS, 256>>>(edge_src, edge_dst, edge_w);

    // t1 = A @ X  needs F16 from branch B
    cudaStreamWaitEvent(0, evFeat, 0);
    k_spmm256h<<<SPMM_BLKS, 256>>>(F16, T1);

    cudaStreamWaitEvent(0, evW, 0);
    {   // h1 = relu(t1 @ W1) -> out[:,128:384] fp32 AND H1 fp16
        dim3 grid(2, MT);
        k_hgemm<<<grid, 256, SMEM_BYTES>>>(T1, W1h, nullptr,
                                           out + 128, 512, H1, 256, NN, 1);
    }
    {   // g = h1 @ W2 -> B3h fp16
        dim3 grid(1, MT);
        k_hgemm<<<grid, 256, SMEM_BYTES>>>(H1, W2h, nullptr,
                                           nullptr, 0, B3h, 128, NN, 0);
    }
    // h2 = A @ g -> out[:,384:512]
    k_spmm128h<<<SPMM_BLKS, 256>>>(B3h, out + 384, 512);

    // ---- join ----
    cudaStreamWaitEvent(0, evB, 0);

    (void)in_sizes; (void)n_in; (void)out_size;
}